// round 1
// baseline (speedup 1.0000x reference)
#include <cuda_runtime.h>

#define S_DIM 64
#define H_DIM 30
#define A_DIM 32
#define BLOCK 128
#define NWARP 4
#define XSTRIDE 65   // pad to kill bank conflicts

// ---------- f32x2 packed helpers (FFMA2 only reachable via PTX) ----------
__device__ __forceinline__ unsigned long long pack2(float lo, float hi) {
    unsigned long long r;
    asm("mov.b64 %0, {%1, %2};" : "=l"(r) : "f"(lo), "f"(hi));
    return r;
}
__device__ __forceinline__ float2 unpack2(unsigned long long v) {
    float2 f;
    asm("mov.b64 {%0, %1}, %2;" : "=f"(f.x), "=f"(f.y) : "l"(v));
    return f;
}
__device__ __forceinline__ unsigned long long ffma2(unsigned long long a,
                                                    unsigned long long b,
                                                    unsigned long long c) {
    unsigned long long d;
    asm("fma.rn.f32x2 %0, %1, %2, %3;" : "=l"(d) : "l"(a), "l"(b), "l"(c));
    return d;
}
__device__ __forceinline__ float tanhfast(float x) {
    float r;
    asm("tanh.approx.f32 %0, %1;" : "=f"(r) : "f"(x));
    return r;
}

// Shared layout (floats):
//  sW1   [64][32]   (cols 30,31 zero-padded)     8192 B
//  sW2   [30][32]                                3840 B
//  sWopt [32][32]                                4096 B
//  sB1[32] sB2[32] sBopt[32] sU[32]               512 B
//  sX    NWARP * 32 * XSTRIDE                   33280 B
// total 49920 B (dynamic smem)

__global__ __launch_bounds__(BLOCK, 4)
void anet_kernel(const float* __restrict__ x,
                 const float* __restrict__ W1, const float* __restrict__ b1,
                 const float* __restrict__ W2, const float* __restrict__ b2,
                 const float* __restrict__ Wopt, const float* __restrict__ bopt,
                 const float* __restrict__ u,
                 float* __restrict__ out, int batch) {
    extern __shared__ float sm[];
    float* sW1   = sm;                       // 2048 floats
    float* sW2   = sW1 + 64 * 32;            // 960
    float* sWopt = sW2 + 30 * 32;            // 1024
    float* sB1   = sWopt + 32 * 32;          // 32
    float* sB2   = sB1 + 32;
    float* sBopt = sB2 + 32;
    float* sU    = sBopt + 32;
    float* sX    = sU + 32;                  // NWARP*32*XSTRIDE

    const int tid  = threadIdx.x;
    const int lane = tid & 31;
    const int warp = tid >> 5;

    // ---- stage weights (transposed: [j][k], k-pairs adjacent) ----
    for (int i = tid; i < H_DIM * S_DIM; i += BLOCK) {
        int k = i / S_DIM, j = i % S_DIM;
        sW1[j * 32 + k] = W1[i];
    }
    for (int i = tid; i < S_DIM * 2; i += BLOCK) {   // zero pad cols 30,31
        int j = i >> 1;
        sW1[j * 32 + 30 + (i & 1)] = 0.0f;
    }
    for (int i = tid; i < A_DIM * H_DIM; i += BLOCK) {
        int k = i / H_DIM, j = i % H_DIM;
        sW2[j * 32 + k] = W2[i];
    }
    for (int i = tid; i < A_DIM * A_DIM; i += BLOCK) {
        int k = i / A_DIM, j = i % A_DIM;
        sWopt[j * 32 + k] = Wopt[i];
    }
    if (tid < 32) {
        sB1[tid]   = (tid < H_DIM) ? b1[tid] : 0.0f;
        sB2[tid]   = b2[tid];
        sBopt[tid] = bopt[tid];
        sU[tid]    = u[tid];
    }
    __syncthreads();

    // ---- stage x tile for this warp: 32 rows x 64 floats, coalesced ----
    const long rowBase = (long)blockIdx.x * BLOCK + warp * 32;
    float* xw = sX + warp * (32 * XSTRIDE);
    {
        const float4* gx = (const float4*)(x + rowBase * S_DIM);
        #pragma unroll
        for (int i = 0; i < 16; i++) {
            int fi = i * 32 + lane;              // float4 index in 32x64 tile
            int r = fi >> 4, c = (fi & 15) << 2;
            float4 v = make_float4(0.f, 0.f, 0.f, 0.f);
            if (rowBase + r < batch) v = gx[fi];
            float* p = xw + r * XSTRIDE + c;
            p[0] = v.x; p[1] = v.y; p[2] = v.z; p[3] = v.w;
        }
    }
    __syncwarp();

    // ---- layer 1: h = relu(x @ W1^T + b1), 15 f32x2 accumulators ----
    unsigned long long acc1[15];
    {
        const unsigned long long* bp = (const unsigned long long*)sB1;
        #pragma unroll
        for (int p = 0; p < 15; p++) acc1[p] = bp[p];
    }
    {
        const float* xr = xw + lane * XSTRIDE;
        #pragma unroll
        for (int j = 0; j < S_DIM; j++) {
            float xj = xr[j];
            unsigned long long xx = pack2(xj, xj);
            const ulonglong2* wr = (const ulonglong2*)(sW1 + j * 32);
            #pragma unroll
            for (int q = 0; q < 7; q++) {
                ulonglong2 w = wr[q];
                acc1[2 * q]     = ffma2(w.x, xx, acc1[2 * q]);
                acc1[2 * q + 1] = ffma2(w.y, xx, acc1[2 * q + 1]);
            }
            ulonglong2 w7 = wr[7];
            acc1[14] = ffma2(w7.x, xx, acc1[14]);
        }
    }
    float h[H_DIM];
    #pragma unroll
    for (int p = 0; p < 15; p++) {
        float2 f = unpack2(acc1[p]);
        h[2 * p]     = fmaxf(f.x, 0.0f);
        h[2 * p + 1] = fmaxf(f.y, 0.0f);
    }

    // ---- layer 2: t = tanh(h @ W2^T + b2) ----
    unsigned long long acc2[16];
    {
        const unsigned long long* bp = (const unsigned long long*)sB2;
        #pragma unroll
        for (int p = 0; p < 16; p++) acc2[p] = bp[p];
    }
    #pragma unroll
    for (int j = 0; j < H_DIM; j++) {
        unsigned long long hh = pack2(h[j], h[j]);
        const ulonglong2* wr = (const ulonglong2*)(sW2 + j * 32);
        #pragma unroll
        for (int q = 0; q < 8; q++) {
            ulonglong2 w = wr[q];
            acc2[2 * q]     = ffma2(w.x, hh, acc2[2 * q]);
            acc2[2 * q + 1] = ffma2(w.y, hh, acc2[2 * q + 1]);
        }
    }
    float t[A_DIM];
    #pragma unroll
    for (int p = 0; p < 16; p++) {
        float2 f = unpack2(acc2[p]);
        t[2 * p]     = tanhfast(f.x);
        t[2 * p + 1] = tanhfast(f.y);
    }

    // ---- layer 3: z = t @ Wopt^T - bopt ----
    unsigned long long acc3[16];
    #pragma unroll
    for (int p = 0; p < 16; p++)
        acc3[p] = pack2(-sBopt[2 * p], -sBopt[2 * p + 1]);
    #pragma unroll
    for (int j = 0; j < A_DIM; j++) {
        unsigned long long tt = pack2(t[j], t[j]);
        const ulonglong2* wr = (const ulonglong2*)(sWopt + j * 32);
        #pragma unroll
        for (int q = 0; q < 8; q++) {
            ulonglong2 w = wr[q];
            acc3[2 * q]     = ffma2(w.x, tt, acc3[2 * q]);
            acc3[2 * q + 1] = ffma2(w.y, tt, acc3[2 * q + 1]);
        }
    }
    float z[A_DIM];
    #pragma unroll
    for (int p = 0; p < 16; p++) {
        float2 f = unpack2(acc3[p]);
        z[2 * p]     = f.x;
        z[2 * p + 1] = f.y;
    }

    // ---- projection onto capped simplex: sum(y)=90, 0<=y<=u ----
    // Fast path: if all coordinates interior, lam = (sum(z)-90)/32 exactly
    // (this is the fixed point the reference's bisection+Newton converges to).
    float y[A_DIM];
    float sumz = 0.0f;
    #pragma unroll
    for (int j = 0; j < A_DIM; j++) sumz += z[j];
    float lam = (sumz - 90.0f) * (1.0f / 32.0f);
    bool interior = true;
    #pragma unroll
    for (int j = 0; j < A_DIM; j++) {
        y[j] = z[j] - lam;
        interior = interior && (y[j] > 0.0f) && (y[j] < sU[j]);
    }
    if (!interior) {
        // faithful reference fallback: 60 bisections + 2 semismooth Newton
        float lo = z[0] - sU[0], hi = z[0];
        #pragma unroll
        for (int j = 1; j < A_DIM; j++) {
            lo = fminf(lo, z[j] - sU[j]);
            hi = fmaxf(hi, z[j]);
        }
        #pragma unroll 1
        for (int it = 0; it < 60; it++) {
            float mid = 0.5f * (lo + hi);
            float g = -90.0f;
            #pragma unroll
            for (int j = 0; j < A_DIM; j++)
                g += fminf(fmaxf(z[j] - mid, 0.0f), sU[j]);
            bool gt = g > 0.0f;
            lo = gt ? mid : lo;
            hi = gt ? hi : mid;
        }
        lam = 0.5f * (lo + hi);
        #pragma unroll 1
        for (int n = 0; n < 2; n++) {
            float g = -90.0f, gp = 0.0f;
            #pragma unroll
            for (int j = 0; j < A_DIM; j++) {
                float d  = z[j] - lam;
                float yj = fminf(fmaxf(d, 0.0f), sU[j]);
                g += yj;
                gp -= ((d > 0.0f) && (d < sU[j])) ? 1.0f : 0.0f;
            }
            lam -= g / ((gp == 0.0f) ? -1.0f : gp);
        }
        #pragma unroll
        for (int j = 0; j < A_DIM; j++)
            y[j] = fminf(fmaxf(z[j] - lam, 0.0f), sU[j]);
    }

    // ---- write-out: stage through shared for coalesced STG.128 ----
    __syncwarp();   // everyone done reading x from xw
    {
        float* yw = xw;
        #pragma unroll
        for (int j = 0; j < A_DIM; j++)
            yw[lane * XSTRIDE + j] = y[j];
        __syncwarp();
        float4* gout = (float4*)(out + rowBase * A_DIM);
        #pragma unroll
        for (int i = 0; i < 8; i++) {
            int fi = i * 32 + lane;              // float4 idx in 32x32 tile
            int r = fi >> 3, c = (fi & 7) << 2;
            const float* p = yw + r * XSTRIDE + c;
            if (rowBase + r < batch) {
                float4 v = make_float4(p[0], p[1], p[2], p[3]);
                gout[fi] = v;
            }
        }
    }
}

extern "C" void kernel_launch(void* const* d_in, const int* in_sizes, int n_in,
                              void* d_out, int out_size) {
    const float* x    = (const float*)d_in[0];
    const float* W1   = (const float*)d_in[1];
    const float* b1   = (const float*)d_in[2];
    const float* W2   = (const float*)d_in[3];
    const float* b2   = (const float*)d_in[4];
    const float* Wopt = (const float*)d_in[5];
    const float* bopt = (const float*)d_in[6];
    const float* u    = (const float*)d_in[7];
    float* out = (float*)d_out;

    int batch = in_sizes[0] / S_DIM;
    int smem = (64 * 32 + 30 * 32 + 32 * 32 + 4 * 32 + NWARP * 32 * XSTRIDE) *
               (int)sizeof(float);  // 49920 B
    cudaFuncSetAttribute(anet_kernel,
                         cudaFuncAttributeMaxDynamicSharedMemorySize, smem);
    int blocks = (batch + BLOCK - 1) / BLOCK;
    anet_kernel<<<blocks, BLOCK, smem>>>(x, W1, b1, W2, b2, Wopt, bopt, u,
                                         out, batch);
}

// round 3
// speedup vs baseline: 2.7598x; 2.7598x over previous
#include <cuda_runtime.h>
#include <cstdint>

#define S_DIM 64
#define A_DIM 32
#define M_TILE 128
#define THREADS 128

__device__ __forceinline__ uint32_t packbf(float lo, float hi) {
    uint32_t r;
    asm("cvt.rn.bf16x2.f32 %0, %1, %2;" : "=r"(r) : "f"(hi), "f"(lo));
    return r;
}
__device__ __forceinline__ float tanhfast(float x) {
    float r; asm("tanh.approx.f32 %0, %1;" : "=f"(r) : "f"(x)); return r;
}
__device__ __forceinline__ void mma16816(float c[4], const uint32_t a[4],
                                         uint32_t b0, uint32_t b1) {
    asm volatile(
        "mma.sync.aligned.m16n8k16.row.col.f32.bf16.bf16.f32 "
        "{%0,%1,%2,%3},{%4,%5,%6,%7},{%8,%9},{%0,%1,%2,%3};"
        : "+f"(c[0]), "+f"(c[1]), "+f"(c[2]), "+f"(c[3])
        : "r"(a[0]), "r"(a[1]), "r"(a[2]), "r"(a[3]), "r"(b0), "r"(b1));
}

// B fragments in shared: 32 frags (L1:16, L2:8, L3:8) x 32 lanes x uint2.
// frag(ks,ni) lane l: t=l&3, n8=l>>2, n=ni*8+n8, k0=ks*16+2t:
//   .x = pack(B[k0][n],B[k0+1][n])  .y = pack(B[k0+8][n],B[k0+9][n]),  B[k][n]=W[n][k]

__global__ __launch_bounds__(THREADS, 4)
void anet_mma(const float* __restrict__ x,
              const float* __restrict__ W1, const float* __restrict__ b1,
              const float* __restrict__ W2, const float* __restrict__ b2,
              const float* __restrict__ Wopt, const float* __restrict__ bopt,
              const float* __restrict__ u,
              float* __restrict__ out, int batch) {
    __shared__ uint2 sBF[32 * 32];
    __shared__ float sb1[32], sb2[32], sbo[32], su[32];

    const int tid  = threadIdx.x;
    const int lane = tid & 31;
    const int wid  = tid >> 5;
    const int t    = lane & 3;
    const int g    = lane >> 2;

    // ---- stage B fragments + biases ----
    for (int idx = tid; idx < 32 * 32; idx += THREADS) {
        int f = idx >> 5, l = idx & 31;
        int lt = l & 3, n8 = l >> 2;
        float v0, v1, v2, v3;
        if (f < 16) {                       // W1: [30][64], pad n>=30
            int k0 = (f >> 2) * 16 + 2 * lt, n = (f & 3) * 8 + n8;
            bool vn = n < 30;
            v0 = vn ? W1[n * 64 + k0]     : 0.f;
            v1 = vn ? W1[n * 64 + k0 + 1] : 0.f;
            v2 = vn ? W1[n * 64 + k0 + 8] : 0.f;
            v3 = vn ? W1[n * 64 + k0 + 9] : 0.f;
        } else if (f < 24) {                // W2: [32][30], pad k>=30
            int fi = f - 16;
            int k0 = (fi >> 2) * 16 + 2 * lt, n = (fi & 3) * 8 + n8;
            v0 = (k0     < 30) ? W2[n * 30 + k0]     : 0.f;
            v1 = (k0 + 1 < 30) ? W2[n * 30 + k0 + 1] : 0.f;
            v2 = (k0 + 8 < 30) ? W2[n * 30 + k0 + 8] : 0.f;
            v3 = (k0 + 9 < 30) ? W2[n * 30 + k0 + 9] : 0.f;
        } else {                            // Wopt: [32][32]
            int fi = f - 24;
            int k0 = (fi >> 2) * 16 + 2 * lt, n = (fi & 3) * 8 + n8;
            v0 = Wopt[n * 32 + k0];     v1 = Wopt[n * 32 + k0 + 1];
            v2 = Wopt[n * 32 + k0 + 8]; v3 = Wopt[n * 32 + k0 + 9];
        }
        sBF[idx] = make_uint2(packbf(v0, v1), packbf(v2, v3));
    }
    if (tid < 32) {
        sb1[tid] = (tid < 30) ? b1[tid] : 0.f;
        sb2[tid] = b2[tid];
        sbo[tid] = bopt[tid];
        su[tid]  = u[tid];
    }
    __syncthreads();

    const long rw = (long)blockIdx.x * M_TILE + wid * 32;   // warp's 32 rows

    // ---- A1 fragments straight from global (sector-aligned LDG.64) ----
    uint32_t a1f[2][4][4];
    #pragma unroll
    for (int mi = 0; mi < 2; mi++) {
        long r0 = rw + mi * 16 + g;
        bool p0 = r0 < batch, p1 = (r0 + 8) < batch;
        const float* base = x + r0 * S_DIM + 2 * t;
        #pragma unroll
        for (int ks = 0; ks < 4; ks++) {
            const float* p = base + ks * 16;
            float2 v0 = p0 ? *(const float2*)(p)              : make_float2(0.f, 0.f);
            float2 v1 = p1 ? *(const float2*)(p + 8 * S_DIM)  : make_float2(0.f, 0.f);
            float2 v2 = p0 ? *(const float2*)(p + 8)          : make_float2(0.f, 0.f);
            float2 v3 = p1 ? *(const float2*)(p + 8 * S_DIM + 8) : make_float2(0.f, 0.f);
            a1f[mi][ks][0] = packbf(v0.x, v0.y);
            a1f[mi][ks][1] = packbf(v1.x, v1.y);
            a1f[mi][ks][2] = packbf(v2.x, v2.y);
            a1f[mi][ks][3] = packbf(v3.x, v3.y);
        }
    }

    // ---- layer 1: D1[32,32] = A1[32,64] @ B1 ----
    float d1[2][4][4] = {};
    #pragma unroll
    for (int ni = 0; ni < 4; ni++) {
        uint2 bf[4];
        #pragma unroll
        for (int ks = 0; ks < 4; ks++) bf[ks] = sBF[(ks * 4 + ni) * 32 + lane];
        #pragma unroll
        for (int mi = 0; mi < 2; mi++)
            #pragma unroll
            for (int ks = 0; ks < 4; ks++)
                mma16816(d1[mi][ni], a1f[mi][ks], bf[ks].x, bf[ks].y);
    }

    // ---- epilogue 1: relu(+b1) -> A2 fragments ----
    uint32_t a2f[2][2][4];
    #pragma unroll
    for (int mi = 0; mi < 2; mi++)
        #pragma unroll
        for (int ks = 0; ks < 2; ks++) {
            #pragma unroll
            for (int h = 0; h < 2; h++) {        // d-tile 2ks+h
                int ni = 2 * ks + h;
                float bl = sb1[ni * 8 + 2 * t], bh = sb1[ni * 8 + 2 * t + 1];
                a2f[mi][ks][2 * h]     = packbf(fmaxf(d1[mi][ni][0] + bl, 0.f),
                                                fmaxf(d1[mi][ni][1] + bh, 0.f));
                a2f[mi][ks][2 * h + 1] = packbf(fmaxf(d1[mi][ni][2] + bl, 0.f),
                                                fmaxf(d1[mi][ni][3] + bh, 0.f));
            }
        }

    // ---- layer 2: D2 = H[32,32] @ B2 ----
    float d2[2][4][4] = {};
    #pragma unroll
    for (int ni = 0; ni < 4; ni++) {
        uint2 bf[2];
        #pragma unroll
        for (int ks = 0; ks < 2; ks++) bf[ks] = sBF[(16 + ks * 4 + ni) * 32 + lane];
        #pragma unroll
        for (int mi = 0; mi < 2; mi++)
            #pragma unroll
            for (int ks = 0; ks < 2; ks++)
                mma16816(d2[mi][ni], a2f[mi][ks], bf[ks].x, bf[ks].y);
    }

    // ---- epilogue 2: tanh(+b2) -> A3 fragments ----
    uint32_t a3f[2][2][4];
    #pragma unroll
    for (int mi = 0; mi < 2; mi++)
        #pragma unroll
        for (int ks = 0; ks < 2; ks++) {
            #pragma unroll
            for (int h = 0; h < 2; h++) {
                int ni = 2 * ks + h;
                float bl = sb2[ni * 8 + 2 * t], bh = sb2[ni * 8 + 2 * t + 1];
                a3f[mi][ks][2 * h]     = packbf(tanhfast(d2[mi][ni][0] + bl),
                                                tanhfast(d2[mi][ni][1] + bh));
                a3f[mi][ks][2 * h + 1] = packbf(tanhfast(d2[mi][ni][2] + bl),
                                                tanhfast(d2[mi][ni][3] + bh));
            }
        }

    // ---- layer 3: D3 = T[32,32] @ B3 ----
    float d3[2][4][4] = {};
    #pragma unroll
    for (int ni = 0; ni < 4; ni++) {
        uint2 bf[2];
        #pragma unroll
        for (int ks = 0; ks < 2; ks++) bf[ks] = sBF[(24 + ks * 4 + ni) * 32 + lane];
        #pragma unroll
        for (int mi = 0; mi < 2; mi++)
            #pragma unroll
            for (int ks = 0; ks < 2; ks++)
                mma16816(d3[mi][ni], a3f[mi][ks], bf[ks].x, bf[ks].y);
    }

    // ---- epilogue 3: z = D3 - bopt; capped-simplex projection per row ----
    // slot s: row = rw + (s>>1)*16 + (s&1)*8 + g; element e=ni*2+j <-> col ni*8+2t+j
    float uv[8], bov[8];
    #pragma unroll
    for (int ni = 0; ni < 4; ni++) {
        uv[2 * ni]      = su[ni * 8 + 2 * t];
        uv[2 * ni + 1]  = su[ni * 8 + 2 * t + 1];
        bov[2 * ni]     = sbo[ni * 8 + 2 * t];
        bov[2 * ni + 1] = sbo[ni * 8 + 2 * t + 1];
    }
    float z[4][8], y[4][8];
    bool allok = true;
    #pragma unroll
    for (int s = 0; s < 4; s++) {
        int mi = s >> 1, h = s & 1;
        float sum = 0.f;
        #pragma unroll
        for (int ni = 0; ni < 4; ni++) {
            z[s][2 * ni]     = d3[mi][ni][2 * h]     - bov[2 * ni];
            z[s][2 * ni + 1] = d3[mi][ni][2 * h + 1] - bov[2 * ni + 1];
            sum += z[s][2 * ni] + z[s][2 * ni + 1];
        }
        sum += __shfl_xor_sync(0xffffffffu, sum, 1);
        sum += __shfl_xor_sync(0xffffffffu, sum, 2);
        float lam = (sum - 90.0f) * (1.0f / 32.0f);
        bool ok = true;
        #pragma unroll
        for (int e = 0; e < 8; e++) {
            float yj = z[s][e] - lam;
            y[s][e] = yj;
            ok = ok && (yj > 0.f) && (yj < uv[e]);
        }
        int oki = ok ? 1 : 0;
        oki &= __shfl_xor_sync(0xffffffffu, oki, 1);
        oki &= __shfl_xor_sync(0xffffffffu, oki, 2);
        allok = allok && (oki != 0);
    }
    if (!__all_sync(0xffffffffu, allok)) {
        // faithful fallback: 60 bisections + 2 semismooth Newton, all rows
        #pragma unroll 1
        for (int s = 0; s < 4; s++) {
            float lo = 1e30f, hi = -1e30f;
            #pragma unroll
            for (int e = 0; e < 8; e++) {
                lo = fminf(lo, z[s][e] - uv[e]);
                hi = fmaxf(hi, z[s][e]);
            }
            lo = fminf(lo, __shfl_xor_sync(0xffffffffu, lo, 1));
            lo = fminf(lo, __shfl_xor_sync(0xffffffffu, lo, 2));
            hi = fmaxf(hi, __shfl_xor_sync(0xffffffffu, hi, 1));
            hi = fmaxf(hi, __shfl_xor_sync(0xffffffffu, hi, 2));
            #pragma unroll 1
            for (int it = 0; it < 60; it++) {
                float mid = 0.5f * (lo + hi);
                float gs = 0.f;
                #pragma unroll
                for (int e = 0; e < 8; e++)
                    gs += fminf(fmaxf(z[s][e] - mid, 0.f), uv[e]);
                gs += __shfl_xor_sync(0xffffffffu, gs, 1);
                gs += __shfl_xor_sync(0xffffffffu, gs, 2);
                bool gt = (gs - 90.f) > 0.f;
                lo = gt ? mid : lo;
                hi = gt ? hi : mid;
            }
            float lam = 0.5f * (lo + hi);
            #pragma unroll 1
            for (int n = 0; n < 2; n++) {
                float gs = 0.f, gp = 0.f;
                #pragma unroll
                for (int e = 0; e < 8; e++) {
                    float dd = z[s][e] - lam;
                    gs += fminf(fmaxf(dd, 0.f), uv[e]);
                    gp -= ((dd > 0.f) && (dd < uv[e])) ? 1.f : 0.f;
                }
                gs += __shfl_xor_sync(0xffffffffu, gs, 1);
                gs += __shfl_xor_sync(0xffffffffu, gs, 2);
                gp += __shfl_xor_sync(0xffffffffu, gp, 1);
                gp += __shfl_xor_sync(0xffffffffu, gp, 2);
                lam -= (gs - 90.f) / ((gp == 0.f) ? -1.f : gp);
            }
            #pragma unroll
            for (int e = 0; e < 8; e++)
                y[s][e] = fminf(fmaxf(z[s][e] - lam, 0.f), uv[e]);
        }
    }

    // ---- store: sector-aligned STG.64 (8 rows x 32B per instruction) ----
    #pragma unroll
    for (int s = 0; s < 4; s++) {
        long r = rw + (s >> 1) * 16 + (s & 1) * 8 + g;
        if (r < batch) {
            float* po = out + r * A_DIM + 2 * t;
            #pragma unroll
            for (int ni = 0; ni < 4; ni++)
                *(float2*)(po + ni * 8) = make_float2(y[s][2 * ni], y[s][2 * ni + 1]);
        }
    }
}

extern "C" void kernel_launch(void* const* d_in, const int* in_sizes, int n_in,
                              void* d_out, int out_size) {
    const float* x    = (const float*)d_in[0];
    const float* W1   = (const float*)d_in[1];
    const float* b1   = (const float*)d_in[2];
    const float* W2   = (const float*)d_in[3];
    const float* b2   = (const float*)d_in[4];
    const float* Wopt = (const float*)d_in[5];
    const float* bopt = (const float*)d_in[6];
    const float* u    = (const float*)d_in[7];
    float* out = (float*)d_out;

    int batch = in_sizes[0] / S_DIM;
    int blocks = (batch + M_TILE - 1) / M_TILE;
    anet_mma<<<blocks, THREADS>>>(x, W1, b1, W2, b2, Wopt, bopt, u, out, batch);
}

// round 4
// speedup vs baseline: 3.4292x; 1.2426x over previous
#include <cuda_runtime.h>
#include <cstdint>

#define S_DIM 64
#define A_DIM 32
#define M_TILE 128
#define THREADS 128

__device__ uint2 g_wfrag[32 * 32];   // prebuilt B fragments
__device__ float g_bias[128];        // b1(pad) | b2 | bopt | u

__device__ __forceinline__ uint32_t packbf(float lo, float hi) {
    uint32_t r;
    asm("cvt.rn.bf16x2.f32 %0, %1, %2;" : "=r"(r) : "f"(hi), "f"(lo));
    return r;
}
__device__ __forceinline__ float tanhfast(float x) {
    float r; asm("tanh.approx.f32 %0, %1;" : "=f"(r) : "f"(x)); return r;
}
__device__ __forceinline__ uint32_t smem_u32(const void* p) {
    uint32_t a;
    asm("{ .reg .u64 t; cvta.to.shared.u64 t, %1; cvt.u32.u64 %0, t; }"
        : "=r"(a) : "l"(p));
    return a;
}
__device__ __forceinline__ void mma16816(float c[4], const uint32_t a[4],
                                         uint32_t b0, uint32_t b1) {
    asm volatile(
        "mma.sync.aligned.m16n8k16.row.col.f32.bf16.bf16.f32 "
        "{%0,%1,%2,%3},{%4,%5,%6,%7},{%8,%9},{%0,%1,%2,%3};"
        : "+f"(c[0]), "+f"(c[1]), "+f"(c[2]), "+f"(c[3])
        : "r"(a[0]), "r"(a[1]), "r"(a[2]), "r"(a[3]), "r"(b0), "r"(b1));
}
__device__ __forceinline__ void ldm_x4(uint32_t r[4], uint32_t addr) {
    asm volatile("ldmatrix.sync.aligned.m8n8.x4.shared.b16 {%0,%1,%2,%3}, [%4];"
                 : "=r"(r[0]), "=r"(r[1]), "=r"(r[2]), "=r"(r[3]) : "r"(addr));
}

// ---------------- pre-kernel: build weight fragments once ----------------
// frag(f) lane l: t=l&3, n8=l>>2. L1: f<16 (ks=f>>2, ni=f&3, K=64);
// L2: f in [16,24); L3: f in [24,32). B[k][n] = W[n][k].
__global__ void anet_prep(const float* __restrict__ W1, const float* __restrict__ b1,
                          const float* __restrict__ W2, const float* __restrict__ b2,
                          const float* __restrict__ Wopt, const float* __restrict__ bopt,
                          const float* __restrict__ u) {
    int tid = threadIdx.x;
    for (int idx = tid; idx < 32 * 32; idx += THREADS) {
        int f = idx >> 5, l = idx & 31;
        int lt = l & 3, n8 = l >> 2;
        float v0, v1, v2, v3;
        if (f < 16) {
            int k0 = (f >> 2) * 16 + 2 * lt, n = (f & 3) * 8 + n8;
            bool vn = n < 30;
            v0 = vn ? W1[n * 64 + k0]     : 0.f;
            v1 = vn ? W1[n * 64 + k0 + 1] : 0.f;
            v2 = vn ? W1[n * 64 + k0 + 8] : 0.f;
            v3 = vn ? W1[n * 64 + k0 + 9] : 0.f;
        } else if (f < 24) {
            int fi = f - 16;
            int k0 = (fi >> 2) * 16 + 2 * lt, n = (fi & 3) * 8 + n8;
            v0 = (k0     < 30) ? W2[n * 30 + k0]     : 0.f;
            v1 = (k0 + 1 < 30) ? W2[n * 30 + k0 + 1] : 0.f;
            v2 = (k0 + 8 < 30) ? W2[n * 30 + k0 + 8] : 0.f;
            v3 = (k0 + 9 < 30) ? W2[n * 30 + k0 + 9] : 0.f;
        } else {
            int fi = f - 24;
            int k0 = (fi >> 2) * 16 + 2 * lt, n = (fi & 3) * 8 + n8;
            v0 = Wopt[n * 32 + k0];     v1 = Wopt[n * 32 + k0 + 1];
            v2 = Wopt[n * 32 + k0 + 8]; v3 = Wopt[n * 32 + k0 + 9];
        }
        g_wfrag[idx] = make_uint2(packbf(v0, v1), packbf(v2, v3));
    }
    if (tid < 32) {
        g_bias[tid]      = (tid < 30) ? b1[tid] : 0.f;
        g_bias[32 + tid] = b2[tid];
        g_bias[64 + tid] = bopt[tid];
        g_bias[96 + tid] = u[tid];
    }
}

// ---------------- main kernel ----------------
__global__ __launch_bounds__(THREADS, 5)
void anet_mma(const float* __restrict__ x, float* __restrict__ out, int batch) {
    __shared__ uint2 sBF[32 * 32];                 // 8 KB
    __shared__ float sBias[128];                   // 512 B
    __shared__ __align__(16) char sBuf[128 * 34 * 4];  // x bf16 (16KB) then y f32

    const int tid  = threadIdx.x;
    const int lane = tid & 31;
    const int wid  = tid >> 5;
    const int t    = lane & 3;
    const int g    = lane >> 2;
    const uint32_t sxb = smem_u32(sBuf);

    // ---- coalesced staging of prebuilt fragments + biases ----
    #pragma unroll
    for (int i = 0; i < 8; i++) sBF[i * THREADS + tid] = g_wfrag[i * THREADS + tid];
    sBias[tid] = g_bias[tid];
    const float* sb1 = sBias;
    const float* sb2 = sBias + 32;
    const float* sbo = sBias + 64;
    const float* su  = sBias + 96;

    // ---- x: coalesced LDG.128 -> bf16 -> swizzled smem [128 rows][128B] ----
    const long rowBase = (long)blockIdx.x * M_TILE;
    {
        const float4* gx = (const float4*)(x + rowBase * S_DIM);
        #pragma unroll
        for (int it = 0; it < 16; it++) {
            int fi = it * THREADS + tid;          // float4 idx in [128][16]
            int r = fi >> 4, c8 = fi & 15;
            float4 v = make_float4(0.f, 0.f, 0.f, 0.f);
            if (rowBase + r < batch) v = gx[fi];
            int c16 = c8 >> 1, half = c8 & 1;
            uint32_t off = (uint32_t)(r * 128 + ((c16 ^ (r & 7)) * 16) + half * 8);
            *(uint2*)(sBuf + off) = make_uint2(packbf(v.x, v.y), packbf(v.z, v.w));
        }
    }
    __syncthreads();

    // ---- A1 fragments via ldmatrix.x4 (conflict-free, swizzled) ----
    uint32_t a1f[2][4][4];
    {
        const int jt = lane >> 3;
        const int rl = (jt & 1) * 8 + (lane & 7);
        #pragma unroll
        for (int mi = 0; mi < 2; mi++) {
            int r = wid * 32 + mi * 16 + rl;
            #pragma unroll
            for (int ks = 0; ks < 4; ks++) {
                int c16 = ks * 2 + (jt >> 1);
                uint32_t addr = sxb + (uint32_t)(r * 128 + ((c16 ^ (r & 7)) * 16));
                ldm_x4(a1f[mi][ks], addr);
            }
        }
    }
    __syncthreads();   // all sBuf(x) reads done; safe to overwrite with y later

    // ---- layer 1: D1[32,32] = A1[32,64] @ B1 ----
    float d1[2][4][4] = {};
    #pragma unroll
    for (int ni = 0; ni < 4; ni++) {
        uint2 bf[4];
        #pragma unroll
        for (int ks = 0; ks < 4; ks++) bf[ks] = sBF[(ks * 4 + ni) * 32 + lane];
        #pragma unroll
        for (int mi = 0; mi < 2; mi++)
            #pragma unroll
            for (int ks = 0; ks < 4; ks++)
                mma16816(d1[mi][ni], a1f[mi][ks], bf[ks].x, bf[ks].y);
    }

    // ---- epilogue 1: relu(+b1) -> A2 fragments ----
    uint32_t a2f[2][2][4];
    #pragma unroll
    for (int mi = 0; mi < 2; mi++)
        #pragma unroll
        for (int ks = 0; ks < 2; ks++)
            #pragma unroll
            for (int h = 0; h < 2; h++) {
                int ni = 2 * ks + h;
                float bl = sb1[ni * 8 + 2 * t], bh = sb1[ni * 8 + 2 * t + 1];
                a2f[mi][ks][2 * h]     = packbf(fmaxf(d1[mi][ni][0] + bl, 0.f),
                                                fmaxf(d1[mi][ni][1] + bh, 0.f));
                a2f[mi][ks][2 * h + 1] = packbf(fmaxf(d1[mi][ni][2] + bl, 0.f),
                                                fmaxf(d1[mi][ni][3] + bh, 0.f));
            }

    // ---- layer 2: D2 = H @ B2 ----
    float d2[2][4][4] = {};
    #pragma unroll
    for (int ni = 0; ni < 4; ni++) {
        uint2 bf[2];
        #pragma unroll
        for (int ks = 0; ks < 2; ks++) bf[ks] = sBF[(16 + ks * 4 + ni) * 32 + lane];
        #pragma unroll
        for (int mi = 0; mi < 2; mi++)
            #pragma unroll
            for (int ks = 0; ks < 2; ks++)
                mma16816(d2[mi][ni], a2f[mi][ks], bf[ks].x, bf[ks].y);
    }

    // ---- epilogue 2: tanh(+b2) -> A3 fragments ----
    uint32_t a3f[2][2][4];
    #pragma unroll
    for (int mi = 0; mi < 2; mi++)
        #pragma unroll
        for (int ks = 0; ks < 2; ks++)
            #pragma unroll
            for (int h = 0; h < 2; h++) {
                int ni = 2 * ks + h;
                float bl = sb2[ni * 8 + 2 * t], bh = sb2[ni * 8 + 2 * t + 1];
                a3f[mi][ks][2 * h]     = packbf(tanhfast(d2[mi][ni][0] + bl),
                                                tanhfast(d2[mi][ni][1] + bh));
                a3f[mi][ks][2 * h + 1] = packbf(tanhfast(d2[mi][ni][2] + bl),
                                                tanhfast(d2[mi][ni][3] + bh));
            }

    // ---- layer 3: D3 = T @ B3 ----
    float d3[2][4][4] = {};
    #pragma unroll
    for (int ni = 0; ni < 4; ni++) {
        uint2 bf[2];
        #pragma unroll
        for (int ks = 0; ks < 2; ks++) bf[ks] = sBF[(24 + ks * 4 + ni) * 32 + lane];
        #pragma unroll
        for (int mi = 0; mi < 2; mi++)
            #pragma unroll
            for (int ks = 0; ks < 2; ks++)
                mma16816(d3[mi][ni], a3f[mi][ks], bf[ks].x, bf[ks].y);
    }

    // ---- epilogue 3: z = D3 - bopt; capped-simplex projection per row ----
    float uv[8], bov[8];
    #pragma unroll
    for (int ni = 0; ni < 4; ni++) {
        uv[2 * ni]      = su[ni * 8 + 2 * t];
        uv[2 * ni + 1]  = su[ni * 8 + 2 * t + 1];
        bov[2 * ni]     = sbo[ni * 8 + 2 * t];
        bov[2 * ni + 1] = sbo[ni * 8 + 2 * t + 1];
    }
    float z[4][8], y[4][8];
    bool allok = true;
    #pragma unroll
    for (int s = 0; s < 4; s++) {
        int mi = s >> 1, h = s & 1;
        float sum = 0.f;
        #pragma unroll
        for (int ni = 0; ni < 4; ni++) {
            z[s][2 * ni]     = d3[mi][ni][2 * h]     - bov[2 * ni];
            z[s][2 * ni + 1] = d3[mi][ni][2 * h + 1] - bov[2 * ni + 1];
            sum += z[s][2 * ni] + z[s][2 * ni + 1];
        }
        sum += __shfl_xor_sync(0xffffffffu, sum, 1);
        sum += __shfl_xor_sync(0xffffffffu, sum, 2);
        float lam = (sum - 90.0f) * (1.0f / 32.0f);
        bool ok = true;
        #pragma unroll
        for (int e = 0; e < 8; e++) {
            float yj = z[s][e] - lam;
            y[s][e] = yj;
            ok = ok && (yj > 0.f) && (yj < uv[e]);
        }
        int oki = ok ? 1 : 0;
        oki &= __shfl_xor_sync(0xffffffffu, oki, 1);
        oki &= __shfl_xor_sync(0xffffffffu, oki, 2);
        allok = allok && (oki != 0);
    }
    if (!__all_sync(0xffffffffu, allok)) {
        #pragma unroll 1
        for (int s = 0; s < 4; s++) {
            float lo = 1e30f, hi = -1e30f;
            #pragma unroll
            for (int e = 0; e < 8; e++) {
                lo = fminf(lo, z[s][e] - uv[e]);
                hi = fmaxf(hi, z[s][e]);
            }
            lo = fminf(lo, __shfl_xor_sync(0xffffffffu, lo, 1));
            lo = fminf(lo, __shfl_xor_sync(0xffffffffu, lo, 2));
            hi = fmaxf(hi, __shfl_xor_sync(0xffffffffu, hi, 1));
            hi = fmaxf(hi, __shfl_xor_sync(0xffffffffu, hi, 2));
            #pragma unroll 1
            for (int it = 0; it < 60; it++) {
                float mid = 0.5f * (lo + hi);
                float gs = 0.f;
                #pragma unroll
                for (int e = 0; e < 8; e++)
                    gs += fminf(fmaxf(z[s][e] - mid, 0.f), uv[e]);
                gs += __shfl_xor_sync(0xffffffffu, gs, 1);
                gs += __shfl_xor_sync(0xffffffffu, gs, 2);
                bool gt = (gs - 90.f) > 0.f;
                lo = gt ? mid : lo;
                hi = gt ? hi : mid;
            }
            float lam = 0.5f * (lo + hi);
            #pragma unroll 1
            for (int n = 0; n < 2; n++) {
                float gs = 0.f, gp = 0.f;
                #pragma unroll
                for (int e = 0; e < 8; e++) {
                    float dd = z[s][e] - lam;
                    gs += fminf(fmaxf(dd, 0.f), uv[e]);
                    gp -= ((dd > 0.f) && (dd < uv[e])) ? 1.f : 0.f;
                }
                gs += __shfl_xor_sync(0xffffffffu, gs, 1);
                gs += __shfl_xor_sync(0xffffffffu, gs, 2);
                gp += __shfl_xor_sync(0xffffffffu, gp, 1);
                gp += __shfl_xor_sync(0xffffffffu, gp, 2);
                lam -= (gs - 90.f) / ((gp == 0.f) ? -1.f : gp);
            }
            #pragma unroll
            for (int e = 0; e < 8; e++)
                y[s][e] = fminf(fmaxf(z[s][e] - lam, 0.f), uv[e]);
        }
    }

    // ---- stage y in smem (stride 34 floats), then coalesced STG.128 ----
    float* sY = (float*)sBuf;
    #pragma unroll
    for (int s = 0; s < 4; s++) {
        int rl = wid * 32 + (s >> 1) * 16 + (s & 1) * 8 + g;
        float* p = sY + rl * 34 + 2 * t;
        #pragma unroll
        for (int ni = 0; ni < 4; ni++)
            *(float2*)(p + ni * 8) = make_float2(y[s][2 * ni], y[s][2 * ni + 1]);
    }
    __syncthreads();
    {
        float4* gout = (float4*)(out + rowBase * A_DIM);
        #pragma unroll
        for (int it = 0; it < 8; it++) {
            int fi = it * THREADS + tid;      // float4 idx in [128][8]
            int r = fi >> 3, c = (fi & 7) * 4;
            if (rowBase + r < batch) {
                const float* p = sY + r * 34 + c;
                gout[fi] = make_float4(p[0], p[1], p[2], p[3]);
            }
        }
    }
}

extern "C" void kernel_launch(void* const* d_in, const int* in_sizes, int n_in,
                              void* d_out, int out_size) {
    const float* x    = (const float*)d_in[0];
    const float* W1   = (const float*)d_in[1];
    const float* b1   = (const float*)d_in[2];
    const float* W2   = (const float*)d_in[3];
    const float* b2   = (const float*)d_in[4];
    const float* Wopt = (const float*)d_in[5];
    const float* bopt = (const float*)d_in[6];
    const float* u    = (const float*)d_in[7];
    float* out = (float*)d_out;

    int batch = in_sizes[0] / S_DIM;
    anet_prep<<<1, THREADS>>>(W1, b1, W2, b2, Wopt, bopt, u);
    int blocks = (batch + M_TILE - 1) / M_TILE;
    anet_mma<<<blocks, THREADS>>>(x, out, batch);
}